// round 13
// baseline (speedup 1.0000x reference)
#include <cuda_runtime.h>
#include <math.h>

// Problem constants
#define G_    64
#define NPG   256
#define EPG   4096
#define NN    (G_*NPG)     // 16384 nodes
#define EE    (G_*EPG)     // 262144 edges
#define HH    4
#define HC    256
#define KDIM  264

typedef unsigned long long ull;

// Scratch (device globals; no allocation allowed)
__device__ __align__(16) float g_ohfeat[NN*8];
__device__ __align__(16) float g_xp[NN*HC];
__device__ __align__(16) float g_al[NN*HH];
__device__ __align__(16) float g_ar[NN*HH];
__device__ __align__(16) float g_W[(size_t)G_*HH*NPG*NPG];  // 67 MB
__device__ __align__(16) float g_C[(size_t)G_*NPG*NPG];     // 17 MB

// packed f32x2 helpers
__device__ __forceinline__ ull pack2(float lo, float hi) {
    ull r; asm("mov.b64 %0, {%1, %2};" : "=l"(r) : "f"(lo), "f"(hi)); return r;
}
__device__ __forceinline__ void unpack2(ull v, float& lo, float& hi) {
    asm("mov.b64 {%0, %1}, %2;" : "=f"(lo), "=f"(hi) : "l"(v));
}
#define FMA2(d, a, b, c) \
    asm("fma.rn.f32x2 %0, %1, %2, %3;" : "=l"(d) : "l"(a), "l"(b), "l"(c))

// ---------------------------------------------------------------------------
// 0a. Zero W
__global__ void __launch_bounds__(256) k_zeroW() {
    size_t idx = (size_t)blockIdx.x * 256 + threadIdx.x;   // 0..1048575
    float4* p = (float4*)g_W;
    float4 z = make_float4(0.f, 0.f, 0.f, 0.f);
#pragma unroll
    for (int i = 0; i < 4; i++) p[idx + (size_t)i * 1048576] = z;
}

// 0b. C = I per graph
__global__ void __launch_bounds__(256) k_initC() {
    size_t idx = (size_t)blockIdx.x * 256 + threadIdx.x;   // 0..262143
    float4* p = (float4*)g_C;
#pragma unroll
    for (int i = 0; i < 4; i++) {
        size_t f = idx + (size_t)i * 262144;       // float4 index
        int row = (int)((f >> 6) & 255);
        int cb  = (int)(f & 63) * 4;
        float4 v;
        v.x = (row == cb + 0) ? 1.f : 0.f;
        v.y = (row == cb + 1) ? 1.f : 0.f;
        v.z = (row == cb + 2) ? 1.f : 0.f;
        v.w = (row == cb + 3) ? 1.f : 0.f;
        p[f] = v;
    }
}

// ---------------------------------------------------------------------------
// 1. Warp-per-node conv (unchanged from R9)
__global__ void __launch_bounds__(128) k_conv(
    const float* __restrict__ oh,
    const float* __restrict__ w1, const float* __restrict__ b1,
    const float* __restrict__ w2, const float* __restrict__ b2,
    const float* __restrict__ fcw, const float* __restrict__ fcb)
{
    __shared__ __align__(16) float z1s[4][32][82];
    __shared__ ull   sw2b[16 * 24];
    __shared__ float sw1[24], sb1[8], sb2[16], sfcw[16 * 8], sfcb[8];
    __shared__ float smean[4][16];

    int t = threadIdx.x;
    int w = t >> 5, l = t & 31;
    int n = blockIdx.x * 4 + w;

    for (int i = t; i < 384; i += 128) {
        int oc = i / 24, j = i % 24;
        float wv = w2[oc * 24 + j];
        sw2b[i] = pack2(wv, wv);
    }
    if (t < 24)  sw1[t] = w1[t];
    if (t < 8)   sb1[t] = b1[t];
    if (t < 16)  sb2[t] = b2[t];
    if (t < 128) sfcw[t] = fcw[t];
    if (t < 8)   sfcb[t] = fcb[t];
    __syncthreads();

    const float* ohrow = oh + (size_t)n * 256;
    float v[8];
    {
        float4 u0 = *(const float4*)&ohrow[l * 8];
        float4 u1 = *(const float4*)&ohrow[l * 8 + 4];
        v[0]=u0.x; v[1]=u0.y; v[2]=u0.z; v[3]=u0.w;
        v[4]=u1.x; v[5]=u1.y; v[6]=u1.z; v[7]=u1.w;
    }

    #define CS(i, j, up) { float _a=v[i], _b=v[j]; \
        v[i] = (up)?fminf(_a,_b):fmaxf(_a,_b); \
        v[j] = (up)?fmaxf(_a,_b):fminf(_a,_b); }
    #define LOCAL3(up) { \
        CS(0,4,up) CS(1,5,up) CS(2,6,up) CS(3,7,up) \
        CS(0,2,up) CS(1,3,up) CS(4,6,up) CS(5,7,up) \
        CS(0,1,up) CS(2,3,up) CS(4,5,up) CS(6,7,up) }
    #define CROSS(jl, up) { bool _lo = ((l & (jl)) == 0); \
        _Pragma("unroll") \
        for (int _i = 0; _i < 8; _i++) { \
            float _o = __shfl_xor_sync(0xffffffffu, v[_i], (jl)); \
            v[_i] = ((_lo == (up)) ? fminf(v[_i], _o) : fmaxf(v[_i], _o)); } }

    CS(0,1,true) CS(2,3,false) CS(4,5,true) CS(6,7,false)
    CS(0,2,true) CS(1,3,true) CS(4,6,false) CS(5,7,false)
    CS(0,1,true) CS(2,3,true) CS(4,5,false) CS(6,7,false)
    { bool up = ((l & 1) == 0);  LOCAL3(up) }
    { bool up = ((l & 2) == 0);  CROSS(1,up) LOCAL3(up) }
    { bool up = ((l & 4) == 0);  CROSS(2,up) CROSS(1,up) LOCAL3(up) }
    { bool up = ((l & 8) == 0);  CROSS(4,up) CROSS(2,up) CROSS(1,up) LOCAL3(up) }
    { bool up = ((l & 16) == 0); CROSS(8,up) CROSS(4,up) CROSS(2,up) CROSS(1,up) LOCAL3(up) }
    { const bool up = true;      CROSS(16,up) CROSS(8,up) CROSS(4,up) CROSS(2,up) CROSS(1,up) LOCAL3(up) }

    float lh = __shfl_up_sync(0xffffffffu, v[7], 1);  if (l == 0)  lh = 0.f;
    float rh = __shfl_down_sync(0xffffffffu, v[0], 1); if (l == 31) rh = 0.f;

#pragma unroll
    for (int ic = 0; ic < 8; ic++) {
        float wm = sw1[ic*3 + 0], wc = sw1[ic*3 + 1], wp = sw1[ic*3 + 2];
        float bb = sb1[ic];
        float z[8];
        z[0] = fmaxf(bb + wm*lh   + wc*v[0] + wp*v[1], 0.f);
#pragma unroll
        for (int i = 1; i < 7; i++)
            z[i] = fmaxf(bb + wm*v[i-1] + wc*v[i] + wp*v[i+1], 0.f);
        z[7] = fmaxf(bb + wm*v[6] + wc*v[7] + wp*rh, 0.f);

        float h0 = __shfl_up_sync(0xffffffffu, z[7], 1);  if (l == 0)  h0 = 0.f;
        float h9 = __shfl_down_sync(0xffffffffu, z[0], 1); if (l == 31) h9 = 0.f;

        float* zr = &z1s[w][l][ic * 10];
        zr[0] = h0;
#pragma unroll
        for (int i = 0; i < 8; i++) zr[i + 1] = z[i];
        zr[9] = h9;
    }

    float mean[16];
#pragma unroll
    for (int oc = 0; oc < 16; oc++) mean[oc] = 0.f;

#pragma unroll
    for (int qq = 0; qq < 2; qq++) {
        ull tap[2][24];
#pragma unroll
        for (int q2 = 0; q2 < 2; q2++) {
            int q = qq * 2 + q2;
#pragma unroll
            for (int ic = 0; ic < 8; ic++) {
                const float* zr = &z1s[w][l][ic * 10];
                ull A = *(const ull*)&zr[2 * q];
                ull B = *(const ull*)&zr[2 * q + 2];
                float a0, a1, b0, b1;
                unpack2(A, a0, a1); unpack2(B, b0, b1);
                tap[q2][ic*3 + 0] = A;
                tap[q2][ic*3 + 1] = pack2(a1, b0);
                tap[q2][ic*3 + 2] = B;
            }
        }
#pragma unroll
        for (int oc = 0; oc < 16; oc++) {
            ull acc0 = pack2(sb2[oc], sb2[oc]);
            ull acc1 = acc0;
#pragma unroll
            for (int j = 0; j < 24; j++) {
                ull wv = sw2b[oc * 24 + j];
                FMA2(acc0, wv, tap[0][j], acc0);
                FMA2(acc1, wv, tap[1][j], acc1);
            }
            float r0, r1, r2, r3;
            unpack2(acc0, r0, r1); unpack2(acc1, r2, r3);
            mean[oc] += fmaxf(r0, 0.f) + fmaxf(r1, 0.f)
                      + fmaxf(r2, 0.f) + fmaxf(r3, 0.f);
        }
    }

    {
        bool lo = (l & 16) == 0;
#pragma unroll
        for (int c2 = 0; c2 < 8; c2++) {
            float give = lo ? mean[c2 + 8] : mean[c2];
            float keep = lo ? mean[c2]     : mean[c2 + 8];
            mean[c2] = keep + __shfl_xor_sync(0xffffffffu, give, 16);
        }
    }
    {
        bool lo = (l & 8) == 0;
#pragma unroll
        for (int c2 = 0; c2 < 4; c2++) {
            float give = lo ? mean[c2 + 4] : mean[c2];
            float keep = lo ? mean[c2]     : mean[c2 + 4];
            mean[c2] = keep + __shfl_xor_sync(0xffffffffu, give, 8);
        }
    }
    {
        bool lo = (l & 4) == 0;
#pragma unroll
        for (int c2 = 0; c2 < 2; c2++) {
            float give = lo ? mean[c2 + 2] : mean[c2];
            float keep = lo ? mean[c2]     : mean[c2 + 2];
            mean[c2] = keep + __shfl_xor_sync(0xffffffffu, give, 4);
        }
    }
    {
        bool lo = (l & 2) == 0;
        float give = lo ? mean[1] : mean[0];
        float keep = lo ? mean[0] : mean[1];
        mean[0] = keep + __shfl_xor_sync(0xffffffffu, give, 2);
    }
    mean[0] += __shfl_xor_sync(0xffffffffu, mean[0], 1);
    if ((l & 1) == 0) smean[w][l >> 1] = mean[0] * (1.0f / 256.0f);
    __syncwarp();

    if (l < 8) {
        float z = sfcb[l];
#pragma unroll
        for (int ic = 0; ic < 16; ic++) z = fmaf(smean[w][ic], sfcw[ic * 8 + l], z);
        g_ohfeat[n * 8 + l] = z;
    }
}

// ---------------------------------------------------------------------------
// 2. Tensor-core GEMM with cp.async double buffering (unchanged from R7).
__device__ __forceinline__ unsigned f2tf32(float f) {
    unsigned u;
    asm("cvt.rna.tf32.f32 %0, %1;" : "=r"(u) : "f"(f));
    return u;
}
__device__ __forceinline__ void cpa16(unsigned d, const void* s, int srcsize) {
    asm volatile("cp.async.cg.shared.global [%0], [%1], 16, %2;"
                 :: "r"(d), "l"(s), "r"(srcsize));
}

#define ASTRIDE 20
#define BSTRIDE 72

__global__ void __launch_bounds__(256) k_gemm(
    const float* __restrict__ x, const float* __restrict__ lw,
    const float* __restrict__ attl, const float* __restrict__ attr)
{
    __shared__ float sA[2][128 * ASTRIDE];
    __shared__ float sB[2][16 * BSTRIDE];
    __shared__ float sattl[64], sattr[64];
    __shared__ float sredl[2][128], sredr[2][128];

    int t  = threadIdx.x;
    int bm = blockIdx.x, bn = blockIdx.y;      // bn == head
    int n0 = bm * 128;
    int w = t >> 5, lane = t & 31;
    int wm = w & 3, wn = w >> 2;
    int gid = lane >> 2, tig = lane & 3;

    if (t < 64) { sattl[t] = attl[bn * 64 + t]; sattr[t] = attr[bn * 64 + t]; }

    unsigned sAaddr[2], sBaddr[2];
    sAaddr[0] = (unsigned)__cvta_generic_to_shared(&sA[0][0]);
    sAaddr[1] = (unsigned)__cvta_generic_to_shared(&sA[1][0]);
    sBaddr[0] = (unsigned)__cvta_generic_to_shared(&sB[0][0]);
    sBaddr[1] = (unsigned)__cvta_generic_to_shared(&sB[1][0]);

    int ar0 = t >> 2,            ac0 = (t & 3) * 4;
    int ar1 = (t + 256) >> 2,    ac1 = (t & 3) * 4;
    int br  = t >> 4,            bc  = (t & 15) * 4;

    auto stage = [&](int kt) {
        int b = kt & 1;
        unsigned da0 = sAaddr[b] + (ar0 * ASTRIDE + ac0) * 4;
        unsigned da1 = sAaddr[b] + (ar1 * ASTRIDE + ac1) * 4;
        unsigned db  = sBaddr[b] + (br  * BSTRIDE + bc ) * 4;
        if (kt < 16) {
            cpa16(da0, x + (size_t)(n0 + ar0) * 256 + kt * 16 + ac0, 16);
            cpa16(da1, x + (size_t)(n0 + ar1) * 256 + kt * 16 + ac1, 16);
            cpa16(db,  lw + (size_t)(kt * 16 + br) * 256 + bn * 64 + bc, 16);
        } else {
            cpa16(da0, (ac0 < 8) ? (const void*)(g_ohfeat + (n0 + ar0) * 8 + ac0)
                                 : (const void*)g_ohfeat, (ac0 < 8) ? 16 : 0);
            cpa16(da1, (ac1 < 8) ? (const void*)(g_ohfeat + (n0 + ar1) * 8 + ac1)
                                 : (const void*)g_ohfeat, (ac1 < 8) ? 16 : 0);
            cpa16(db,  (br < 8) ? (const void*)(lw + (size_t)(256 + br) * 256 + bn * 64 + bc)
                                : (const void*)lw, (br < 8) ? 16 : 0);
        }
        asm volatile("cp.async.commit_group;");
    };

    float c[2][4][4];
#pragma unroll
    for (int mt = 0; mt < 2; mt++)
#pragma unroll
        for (int nt = 0; nt < 4; nt++)
#pragma unroll
            for (int q = 0; q < 4; q++) c[mt][nt][q] = 0.f;

    stage(0);

    for (int kt = 0; kt < 17; kt++) {
        asm volatile("cp.async.wait_group 0;");
        __syncthreads();
        if (kt < 16) stage(kt + 1);

        const float* A = sA[kt & 1];
        const float* B = sB[kt & 1];
#pragma unroll
        for (int ks = 0; ks < 2; ks++) {
            int kbv = ks * 8;
            unsigned a[2][4], b[4][2];
#pragma unroll
            for (int mt = 0; mt < 2; mt++) {
                int m = wm * 32 + mt * 16 + gid;
                a[mt][0] = f2tf32(A[m       * ASTRIDE + kbv + tig]);
                a[mt][1] = f2tf32(A[(m + 8) * ASTRIDE + kbv + tig]);
                a[mt][2] = f2tf32(A[m       * ASTRIDE + kbv + tig + 4]);
                a[mt][3] = f2tf32(A[(m + 8) * ASTRIDE + kbv + tig + 4]);
            }
#pragma unroll
            for (int nt = 0; nt < 4; nt++) {
                int n = wn * 32 + nt * 8 + gid;
                b[nt][0] = f2tf32(B[(kbv + tig)     * BSTRIDE + n]);
                b[nt][1] = f2tf32(B[(kbv + tig + 4) * BSTRIDE + n]);
            }
#pragma unroll
            for (int mt = 0; mt < 2; mt++)
#pragma unroll
                for (int nt = 0; nt < 4; nt++)
                    asm volatile(
                        "mma.sync.aligned.m16n8k8.row.col.f32.tf32.tf32.f32 "
                        "{%0,%1,%2,%3}, {%4,%5,%6,%7}, {%8,%9}, {%0,%1,%2,%3};"
                        : "+f"(c[mt][nt][0]), "+f"(c[mt][nt][1]),
                          "+f"(c[mt][nt][2]), "+f"(c[mt][nt][3])
                        : "r"(a[mt][0]), "r"(a[mt][1]), "r"(a[mt][2]), "r"(a[mt][3]),
                          "r"(b[nt][0]), "r"(b[nt][1]));
        }
        __syncthreads();
    }

#pragma unroll
    for (int mt = 0; mt < 2; mt++) {
        int r0 = wm * 32 + mt * 16 + gid;
#pragma unroll
        for (int nt = 0; nt < 4; nt++) {
            int gcol = bn * 64 + wn * 32 + nt * 8 + tig * 2;
            *(float2*)&g_xp[(size_t)(n0 + r0)     * 256 + gcol] =
                make_float2(c[mt][nt][0], c[mt][nt][1]);
            *(float2*)&g_xp[(size_t)(n0 + r0 + 8) * 256 + gcol] =
                make_float2(c[mt][nt][2], c[mt][nt][3]);
        }
    }

    float pl[4] = {0.f, 0.f, 0.f, 0.f};
    float pr[4] = {0.f, 0.f, 0.f, 0.f};
#pragma unroll
    for (int mt = 0; mt < 2; mt++)
#pragma unroll
        for (int nt = 0; nt < 4; nt++) {
            int cl = wn * 32 + nt * 8 + tig * 2;
            float wl0 = sattl[cl], wl1 = sattl[cl + 1];
            float wr0 = sattr[cl], wr1 = sattr[cl + 1];
            pl[mt*2+0] += c[mt][nt][0]*wl0 + c[mt][nt][1]*wl1;
            pl[mt*2+1] += c[mt][nt][2]*wl0 + c[mt][nt][3]*wl1;
            pr[mt*2+0] += c[mt][nt][0]*wr0 + c[mt][nt][1]*wr1;
            pr[mt*2+1] += c[mt][nt][2]*wr0 + c[mt][nt][3]*wr1;
        }
#pragma unroll
    for (int o = 2; o > 0; o >>= 1)
#pragma unroll
        for (int q = 0; q < 4; q++) {
            pl[q] += __shfl_down_sync(0xffffffffu, pl[q], o, 4);
            pr[q] += __shfl_down_sync(0xffffffffu, pr[q], o, 4);
        }
    if (tig == 0) {
#pragma unroll
        for (int mt = 0; mt < 2; mt++)
#pragma unroll
            for (int sb = 0; sb < 2; sb++) {
                int r = wm * 32 + mt * 16 + sb * 8 + gid;
                sredl[wn][r] = pl[mt*2+sb];
                sredr[wn][r] = pr[mt*2+sb];
            }
    }
    __syncthreads();
    if (t < 128) {
        g_al[(n0 + t) * 4 + bn] = sredl[0][t] + sredl[1][t];
        g_ar[(n0 + t) * 4 + bn] = sredr[0][t] + sredr[1][t];
    }
}

// ---------------------------------------------------------------------------
// 3. Per-edge build of W (4 heads) and C (counts) via spread atomics.
__global__ void __launch_bounds__(256) k_edge(const int* __restrict__ adjs) {
    int e = blockIdx.x * 256 + threadIdx.x;
    int g = e >> 12, le = e & (EPG - 1);
    int base = g * 2 * EPG;
    int src = adjs[base + le];
    int dst = adjs[base + EPG + le];

    atomicAdd(&g_C[((size_t)g << 16) + dst * 256 + src], 1.0f);

    float4 al = *(const float4*)&g_al[(g * 256 + src) * 4];
    float4 ar = *(const float4*)&g_ar[(g * 256 + dst) * 4];
    float* Wp = g_W + ((size_t)(g * 4) << 16) + dst * 256 + src;
    float l0 = al.x + ar.x, l1 = al.y + ar.y, l2 = al.z + ar.z, l3 = al.w + ar.w;
    l0 = (l0 > 0.f) ? l0 : 0.2f * l0;
    l1 = (l1 > 0.f) ? l1 : 0.2f * l1;
    l2 = (l2 > 0.f) ? l2 : 0.2f * l2;
    l3 = (l3 > 0.f) ? l3 : 0.2f * l3;
    atomicAdd(Wp,               __expf(l0));
    atomicAdd(Wp + (1 << 16),   __expf(l1));
    atomicAdd(Wp + (2 << 16),   __expf(l2));
    atomicAdd(Wp + (3 << 16),   __expf(l3));
}

// ---------------------------------------------------------------------------
// 4. Per-graph aggregation GEMMs:  [256x256] @ [256x64], tf32, cp.async.
//    mode 0: A = W[g,head q], B = xp cols q*64, softmax epilogue
//    mode 1: A = C[g] (incl. +I), B = oh cols q*64, plain store
//    Dynamic smem: A tiles 2*256*20, B tiles 2*16*72 (50176 bytes).
#define BSTR2 72
#define AGG_DYN_SMEM ((2*256*ASTRIDE + 2*16*BSTR2) * 4)
__global__ void __launch_bounds__(256) k_aggmm(
    const float* __restrict__ oh,
    const float* __restrict__ bias,
    float* __restrict__ out)
{
    extern __shared__ float dyn[];
    float* sAbuf = dyn;                         // [2][256*ASTRIDE]
    float* sBbuf = dyn + 2 * 256 * ASTRIDE;     // [2][16*BSTR2]
    __shared__ float sden[256];
    __shared__ float sb[64];

    int t = threadIdx.x;
    int g = blockIdx.x, q = blockIdx.y, mode = blockIdx.z;
    int w = t >> 5, lane = t & 31;
    int wm = w & 3, wn = w >> 2;
    int gid = lane >> 2, tig = lane & 3;

    const float* Abase = (mode == 0) ? g_W + ((size_t)(g * 4 + q) << 16)
                                     : g_C + ((size_t)g << 16);
    const float* Bbase = (mode == 0) ? g_xp + (size_t)(g * 256) * 256 + q * 64
                                     : oh + ((size_t)g << 16) + q * 64;

    if (mode == 0 && t < 64) sb[t] = bias[q * 64 + t];

    unsigned sAaddr = (unsigned)__cvta_generic_to_shared(sAbuf);
    unsigned sBaddr = (unsigned)__cvta_generic_to_shared(sBbuf);

    int br = t >> 4, bc = (t & 15) * 4;

    auto stage = [&](int kt) {
        int b = kt & 1;
        unsigned abuf = sAaddr + b * (256 * ASTRIDE) * 4;
        unsigned bbuf = sBaddr + b * (16 * BSTR2) * 4;
#pragma unroll
        for (int i = 0; i < 4; i++) {
            int idx = i * 256 + t;               // 0..1023 float4s
            int r = idx >> 2, k4 = (idx & 3) * 4;
            cpa16(abuf + (r * ASTRIDE + k4) * 4,
                  Abase + (size_t)r * 256 + kt * 16 + k4, 16);
        }
        cpa16(bbuf + (br * BSTR2 + bc) * 4,
              Bbase + (size_t)(kt * 16 + br) * 256 + bc, 16);
        asm volatile("cp.async.commit_group;");
    };

    float c[4][4][4];
#pragma unroll
    for (int mt = 0; mt < 4; mt++)
#pragma unroll
        for (int nt = 0; nt < 4; nt++)
#pragma unroll
            for (int qq = 0; qq < 4; qq++) c[mt][nt][qq] = 0.f;
    float den = 0.f;

    stage(0);

    for (int kt = 0; kt < 16; kt++) {
        asm volatile("cp.async.wait_group 0;");
        __syncthreads();
        if (kt < 15) stage(kt + 1);

        const float* A = sAbuf + (kt & 1) * (256 * ASTRIDE);
        const float* B = sBbuf + (kt & 1) * (16 * BSTR2);

        // den partial: thread t owns dst row t
        {
            const float* ar = A + t * ASTRIDE;
#pragma unroll
            for (int k = 0; k < 16; k++) den += ar[k];
        }

#pragma unroll
        for (int ks = 0; ks < 2; ks++) {
            int kbv = ks * 8;
            unsigned a[4][4], b[4][2];
#pragma unroll
            for (int mt = 0; mt < 4; mt++) {
                int m = wm * 64 + mt * 16 + gid;
                a[mt][0] = f2tf32(A[m       * ASTRIDE + kbv + tig]);
                a[mt][1] = f2tf32(A[(m + 8) * ASTRIDE + kbv + tig]);
                a[mt][2] = f2tf32(A[m       * ASTRIDE + kbv + tig + 4]);
                a[mt][3] = f2tf32(A[(m + 8) * ASTRIDE + kbv + tig + 4]);
            }
#pragma unroll
            for (int nt = 0; nt < 4; nt++) {
                int n = wn * 32 + nt * 8 + gid;
                b[nt][0] = f2tf32(B[(kbv + tig)     * BSTR2 + n]);
                b[nt][1] = f2tf32(B[(kbv + tig + 4) * BSTR2 + n]);
            }
#pragma unroll
            for (int mt = 0; mt < 4; mt++)
#pragma unroll
                for (int nt = 0; nt < 4; nt++)
                    asm volatile(
                        "mma.sync.aligned.m16n8k8.row.col.f32.tf32.tf32.f32 "
                        "{%0,%1,%2,%3}, {%4,%5,%6,%7}, {%8,%9}, {%0,%1,%2,%3};"
                        : "+f"(c[mt][nt][0]), "+f"(c[mt][nt][1]),
                          "+f"(c[mt][nt][2]), "+f"(c[mt][nt][3])
                        : "r"(a[mt][0]), "r"(a[mt][1]), "r"(a[mt][2]), "r"(a[mt][3]),
                          "r"(b[nt][0]), "r"(b[nt][1]));
        }
        __syncthreads();
    }

    sden[t] = den;
    __syncthreads();

#pragma unroll
    for (int mt = 0; mt < 4; mt++) {
        int r = wm * 64 + mt * 16 + gid;
#pragma unroll
        for (int nt = 0; nt < 4; nt++) {
            int col = wn * 32 + nt * 8 + tig * 2;
            if (mode == 0) {
                float d0 = sden[r]     + 1e-16f;
                float d1 = sden[r + 8] + 1e-16f;
                float b0 = sb[col], b1 = sb[col + 1];
                *(float2*)&out[(size_t)(g * 256 + r)     * 256 + q * 64 + col] =
                    make_float2(c[mt][nt][0] / d0 + b0, c[mt][nt][1] / d0 + b1);
                *(float2*)&out[(size_t)(g * 256 + r + 8) * 256 + q * 64 + col] =
                    make_float2(c[mt][nt][2] / d1 + b0, c[mt][nt][3] / d1 + b1);
            } else {
                size_t base = (size_t)NN * 256 + ((size_t)g << 16)
                            + (size_t)r * 256 + q * 64 + col;
                *(float2*)&out[base]           = make_float2(c[mt][nt][0], c[mt][nt][1]);
                *(float2*)&out[base + 8 * 256] = make_float2(c[mt][nt][2], c[mt][nt][3]);
            }
        }
    }
}

// ---------------------------------------------------------------------------
extern "C" void kernel_launch(void* const* d_in, const int* in_sizes, int n_in,
                              void* d_out, int out_size)
{
    const float* x     = (const float*)d_in[0];
    const float* oh    = (const float*)d_in[1];
    const int*   adjs  = (const int*)d_in[2];
    const float* lin_w = (const float*)d_in[3];
    const float* att_l = (const float*)d_in[4];
    const float* att_r = (const float*)d_in[5];
    const float* bias  = (const float*)d_in[6];
    const float* c1w   = (const float*)d_in[7];
    const float* c1b   = (const float*)d_in[8];
    const float* c2w   = (const float*)d_in[9];
    const float* c2b   = (const float*)d_in[10];
    const float* fcw   = (const float*)d_in[11];
    const float* fcb   = (const float*)d_in[12];
    float* out = (float*)d_out;

    cudaFuncSetAttribute(k_aggmm, cudaFuncAttributeMaxDynamicSharedMemorySize,
                         AGG_DYN_SMEM);

    k_zeroW<<<4096, 256>>>();
    k_initC<<<1024, 256>>>();

    k_conv<<<NN / 4, 128>>>(oh, c1w, c1b, c2w, c2b, fcw, fcb);
    dim3 ggrid(NN / 128, 4);
    k_gemm<<<ggrid, 256>>>(x, lin_w, att_l, att_r);

    k_edge<<<EE / 256, 256>>>(adjs);

    dim3 agrid(G_, 4, 2);
    k_aggmm<<<agrid, 256, AGG_DYN_SMEM>>>(oh, bias, out);
}

// round 14
// speedup vs baseline: 1.2325x; 1.2325x over previous
#include <cuda_runtime.h>
#include <math.h>

// Problem constants
#define G_    64
#define NPG   256
#define EPG   4096
#define NN    (G_*NPG)     // 16384 nodes
#define EE    (G_*EPG)     // 262144 edges
#define HH    4
#define HC    256
#define KDIM  264

typedef unsigned long long ull;

// Scratch (device globals; no allocation allowed)
__device__ int   g_deg[NN];
__device__ int   g_off[NN];
__device__ int   g_cur[NN];
__device__ int   g_esrc[EE];
__device__ __align__(16) float g_ohfeat[NN*8];
__device__ __align__(16) float g_xp[NN*HC];
__device__ __align__(16) float g_al[NN*HH];
__device__ __align__(16) float g_ar[NN*HH];

// packed f32x2 helpers
__device__ __forceinline__ ull pack2(float lo, float hi) {
    ull r; asm("mov.b64 %0, {%1, %2};" : "=l"(r) : "f"(lo), "f"(hi)); return r;
}
__device__ __forceinline__ void unpack2(ull v, float& lo, float& hi) {
    asm("mov.b64 {%0, %1}, %2;" : "=f"(lo), "=f"(hi) : "l"(v));
}
#define FMA2(d, a, b, c) \
    asm("fma.rn.f32x2 %0, %1, %2, %3;" : "=l"(d) : "l"(a), "l"(b), "l"(c))

// ---------------------------------------------------------------------------
// 1. Fused CSR prefix: per-graph smem histogram + scan (one block per graph)
__global__ void __launch_bounds__(256) k_csr(const int* __restrict__ adjs) {
    __shared__ int sdeg[NPG];
    __shared__ int s[NPG];
    int g = blockIdx.x, t = threadIdx.x;
    sdeg[t] = 0;
    __syncthreads();
    const int* dsts = adjs + g * 2 * EPG + EPG;
#pragma unroll 4
    for (int e = t; e < EPG; e += 256)
        atomicAdd(&sdeg[dsts[e]], 1);
    __syncthreads();
    int d = sdeg[t];
    s[t] = d;
    for (int o = 1; o < NPG; o <<= 1) {
        __syncthreads();
        int v = (t >= o) ? s[t - o] : 0;
        __syncthreads();
        s[t] += v;
    }
    __syncthreads();
    int off = g * EPG + s[t] - d;   // exclusive prefix + graph base
    g_deg[g * NPG + t] = d;
    g_off[g * NPG + t] = off;
    g_cur[g * NPG + t] = off;
}

// 2. Scatter source ids into CSR slots
__global__ void k_scatter(const int* __restrict__ adjs) {
    int e  = blockIdx.x * 256 + threadIdx.x;
    if (e >= EE) return;
    int g  = e >> 12;
    int le = e & (EPG - 1);
    int base = g * 2 * EPG;
    int src = adjs[base + le];
    int dst = adjs[base + EPG + le];
    int pos = atomicAdd(&g_cur[g * NPG + dst], 1);
    g_esrc[pos] = g * NPG + src;
}

// ---------------------------------------------------------------------------
// 3. Warp-per-node conv (unchanged from R9)
__global__ void __launch_bounds__(128) k_conv(
    const float* __restrict__ oh,
    const float* __restrict__ w1, const float* __restrict__ b1,
    const float* __restrict__ w2, const float* __restrict__ b2,
    const float* __restrict__ fcw, const float* __restrict__ fcb)
{
    __shared__ __align__(16) float z1s[4][32][82];
    __shared__ ull   sw2b[16 * 24];
    __shared__ float sw1[24], sb1[8], sb2[16], sfcw[16 * 8], sfcb[8];
    __shared__ float smean[4][16];

    int t = threadIdx.x;
    int w = t >> 5, l = t & 31;
    int n = blockIdx.x * 4 + w;

    for (int i = t; i < 384; i += 128) {
        int oc = i / 24, j = i % 24;
        float wv = w2[oc * 24 + j];
        sw2b[i] = pack2(wv, wv);
    }
    if (t < 24)  sw1[t] = w1[t];
    if (t < 8)   sb1[t] = b1[t];
    if (t < 16)  sb2[t] = b2[t];
    if (t < 128) sfcw[t] = fcw[t];
    if (t < 8)   sfcb[t] = fcb[t];
    __syncthreads();

    const float* ohrow = oh + (size_t)n * 256;
    float v[8];
    {
        float4 u0 = *(const float4*)&ohrow[l * 8];
        float4 u1 = *(const float4*)&ohrow[l * 8 + 4];
        v[0]=u0.x; v[1]=u0.y; v[2]=u0.z; v[3]=u0.w;
        v[4]=u1.x; v[5]=u1.y; v[6]=u1.z; v[7]=u1.w;
    }

    #define CS(i, j, up) { float _a=v[i], _b=v[j]; \
        v[i] = (up)?fminf(_a,_b):fmaxf(_a,_b); \
        v[j] = (up)?fmaxf(_a,_b):fminf(_a,_b); }
    #define LOCAL3(up) { \
        CS(0,4,up) CS(1,5,up) CS(2,6,up) CS(3,7,up) \
        CS(0,2,up) CS(1,3,up) CS(4,6,up) CS(5,7,up) \
        CS(0,1,up) CS(2,3,up) CS(4,5,up) CS(6,7,up) }
    #define CROSS(jl, up) { bool _lo = ((l & (jl)) == 0); \
        _Pragma("unroll") \
        for (int _i = 0; _i < 8; _i++) { \
            float _o = __shfl_xor_sync(0xffffffffu, v[_i], (jl)); \
            v[_i] = ((_lo == (up)) ? fminf(v[_i], _o) : fmaxf(v[_i], _o)); } }

    CS(0,1,true) CS(2,3,false) CS(4,5,true) CS(6,7,false)
    CS(0,2,true) CS(1,3,true) CS(4,6,false) CS(5,7,false)
    CS(0,1,true) CS(2,3,true) CS(4,5,false) CS(6,7,false)
    { bool up = ((l & 1) == 0);  LOCAL3(up) }
    { bool up = ((l & 2) == 0);  CROSS(1,up) LOCAL3(up) }
    { bool up = ((l & 4) == 0);  CROSS(2,up) CROSS(1,up) LOCAL3(up) }
    { bool up = ((l & 8) == 0);  CROSS(4,up) CROSS(2,up) CROSS(1,up) LOCAL3(up) }
    { bool up = ((l & 16) == 0); CROSS(8,up) CROSS(4,up) CROSS(2,up) CROSS(1,up) LOCAL3(up) }
    { const bool up = true;      CROSS(16,up) CROSS(8,up) CROSS(4,up) CROSS(2,up) CROSS(1,up) LOCAL3(up) }

    float lh = __shfl_up_sync(0xffffffffu, v[7], 1);  if (l == 0)  lh = 0.f;
    float rh = __shfl_down_sync(0xffffffffu, v[0], 1); if (l == 31) rh = 0.f;

#pragma unroll
    for (int ic = 0; ic < 8; ic++) {
        float wm = sw1[ic*3 + 0], wc = sw1[ic*3 + 1], wp = sw1[ic*3 + 2];
        float bb = sb1[ic];
        float z[8];
        z[0] = fmaxf(bb + wm*lh   + wc*v[0] + wp*v[1], 0.f);
#pragma unroll
        for (int i = 1; i < 7; i++)
            z[i] = fmaxf(bb + wm*v[i-1] + wc*v[i] + wp*v[i+1], 0.f);
        z[7] = fmaxf(bb + wm*v[6] + wc*v[7] + wp*rh, 0.f);

        float h0 = __shfl_up_sync(0xffffffffu, z[7], 1);  if (l == 0)  h0 = 0.f;
        float h9 = __shfl_down_sync(0xffffffffu, z[0], 1); if (l == 31) h9 = 0.f;

        float* zr = &z1s[w][l][ic * 10];
        zr[0] = h0;
#pragma unroll
        for (int i = 0; i < 8; i++) zr[i + 1] = z[i];
        zr[9] = h9;
    }

    float mean[16];
#pragma unroll
    for (int oc = 0; oc < 16; oc++) mean[oc] = 0.f;

#pragma unroll
    for (int qq = 0; qq < 2; qq++) {
        ull tap[2][24];
#pragma unroll
        for (int q2 = 0; q2 < 2; q2++) {
            int q = qq * 2 + q2;
#pragma unroll
            for (int ic = 0; ic < 8; ic++) {
                const float* zr = &z1s[w][l][ic * 10];
                ull A = *(const ull*)&zr[2 * q];
                ull B = *(const ull*)&zr[2 * q + 2];
                float a0, a1, b0, b1;
                unpack2(A, a0, a1); unpack2(B, b0, b1);
                tap[q2][ic*3 + 0] = A;
                tap[q2][ic*3 + 1] = pack2(a1, b0);
                tap[q2][ic*3 + 2] = B;
            }
        }
#pragma unroll
        for (int oc = 0; oc < 16; oc++) {
            ull acc0 = pack2(sb2[oc], sb2[oc]);
            ull acc1 = acc0;
#pragma unroll
            for (int j = 0; j < 24; j++) {
                ull wv = sw2b[oc * 24 + j];
                FMA2(acc0, wv, tap[0][j], acc0);
                FMA2(acc1, wv, tap[1][j], acc1);
            }
            float r0, r1, r2, r3;
            unpack2(acc0, r0, r1); unpack2(acc1, r2, r3);
            mean[oc] += fmaxf(r0, 0.f) + fmaxf(r1, 0.f)
                      + fmaxf(r2, 0.f) + fmaxf(r3, 0.f);
        }
    }

    {
        bool lo = (l & 16) == 0;
#pragma unroll
        for (int c2 = 0; c2 < 8; c2++) {
            float give = lo ? mean[c2 + 8] : mean[c2];
            float keep = lo ? mean[c2]     : mean[c2 + 8];
            mean[c2] = keep + __shfl_xor_sync(0xffffffffu, give, 16);
        }
    }
    {
        bool lo = (l & 8) == 0;
#pragma unroll
        for (int c2 = 0; c2 < 4; c2++) {
            float give = lo ? mean[c2 + 4] : mean[c2];
            float keep = lo ? mean[c2]     : mean[c2 + 4];
            mean[c2] = keep + __shfl_xor_sync(0xffffffffu, give, 8);
        }
    }
    {
        bool lo = (l & 4) == 0;
#pragma unroll
        for (int c2 = 0; c2 < 2; c2++) {
            float give = lo ? mean[c2 + 2] : mean[c2];
            float keep = lo ? mean[c2]     : mean[c2 + 2];
            mean[c2] = keep + __shfl_xor_sync(0xffffffffu, give, 4);
        }
    }
    {
        bool lo = (l & 2) == 0;
        float give = lo ? mean[1] : mean[0];
        float keep = lo ? mean[0] : mean[1];
        mean[0] = keep + __shfl_xor_sync(0xffffffffu, give, 2);
    }
    mean[0] += __shfl_xor_sync(0xffffffffu, mean[0], 1);
    if ((l & 1) == 0) smean[w][l >> 1] = mean[0] * (1.0f / 256.0f);
    __syncwarp();

    if (l < 8) {
        float z = sfcb[l];
#pragma unroll
        for (int ic = 0; ic < 16; ic++) z = fmaf(smean[w][ic], sfcw[ic * 8 + l], z);
        g_ohfeat[n * 8 + l] = z;
    }
}

// ---------------------------------------------------------------------------
// 4. Tensor-core GEMM with cp.async double buffering (unchanged from R7).
__device__ __forceinline__ unsigned f2tf32(float f) {
    unsigned u;
    asm("cvt.rna.tf32.f32 %0, %1;" : "=r"(u) : "f"(f));
    return u;
}
__device__ __forceinline__ void cpa16(unsigned d, const void* s, int srcsize) {
    asm volatile("cp.async.cg.shared.global [%0], [%1], 16, %2;"
                 :: "r"(d), "l"(s), "r"(srcsize));
}

#define ASTRIDE 20
#define BSTRIDE 72

__global__ void __launch_bounds__(256) k_gemm(
    const float* __restrict__ x, const float* __restrict__ lw,
    const float* __restrict__ attl, const float* __restrict__ attr)
{
    __shared__ float sA[2][128 * ASTRIDE];
    __shared__ float sB[2][16 * BSTRIDE];
    __shared__ float sattl[64], sattr[64];
    __shared__ float sredl[2][128], sredr[2][128];

    int t  = threadIdx.x;
    int bm = blockIdx.x, bn = blockIdx.y;      // bn == head
    int n0 = bm * 128;
    int w = t >> 5, lane = t & 31;
    int wm = w & 3, wn = w >> 2;
    int gid = lane >> 2, tig = lane & 3;

    if (t < 64) { sattl[t] = attl[bn * 64 + t]; sattr[t] = attr[bn * 64 + t]; }

    unsigned sAaddr[2], sBaddr[2];
    sAaddr[0] = (unsigned)__cvta_generic_to_shared(&sA[0][0]);
    sAaddr[1] = (unsigned)__cvta_generic_to_shared(&sA[1][0]);
    sBaddr[0] = (unsigned)__cvta_generic_to_shared(&sB[0][0]);
    sBaddr[1] = (unsigned)__cvta_generic_to_shared(&sB[1][0]);

    int ar0 = t >> 2,            ac0 = (t & 3) * 4;
    int ar1 = (t + 256) >> 2,    ac1 = (t & 3) * 4;
    int br  = t >> 4,            bc  = (t & 15) * 4;

    auto stage = [&](int kt) {
        int b = kt & 1;
        unsigned da0 = sAaddr[b] + (ar0 * ASTRIDE + ac0) * 4;
        unsigned da1 = sAaddr[b] + (ar1 * ASTRIDE + ac1) * 4;
        unsigned db  = sBaddr[b] + (br  * BSTRIDE + bc ) * 4;
        if (kt < 16) {
            cpa16(da0, x + (size_t)(n0 + ar0) * 256 + kt * 16 + ac0, 16);
            cpa16(da1, x + (size_t)(n0 + ar1) * 256 + kt * 16 + ac1, 16);
            cpa16(db,  lw + (size_t)(kt * 16 + br) * 256 + bn * 64 + bc, 16);
        } else {
            cpa16(da0, (ac0 < 8) ? (const void*)(g_ohfeat + (n0 + ar0) * 8 + ac0)
                                 : (const void*)g_ohfeat, (ac0 < 8) ? 16 : 0);
            cpa16(da1, (ac1 < 8) ? (const void*)(g_ohfeat + (n0 + ar1) * 8 + ac1)
                                 : (const void*)g_ohfeat, (ac1 < 8) ? 16 : 0);
            cpa16(db,  (br < 8) ? (const void*)(lw + (size_t)(256 + br) * 256 + bn * 64 + bc)
                                : (const void*)lw, (br < 8) ? 16 : 0);
        }
        asm volatile("cp.async.commit_group;");
    };

    float c[2][4][4];
#pragma unroll
    for (int mt = 0; mt < 2; mt++)
#pragma unroll
        for (int nt = 0; nt < 4; nt++)
#pragma unroll
            for (int q = 0; q < 4; q++) c[mt][nt][q] = 0.f;

    stage(0);

    for (int kt = 0; kt < 17; kt++) {
        asm volatile("cp.async.wait_group 0;");
        __syncthreads();
        if (kt < 16) stage(kt + 1);

        const float* A = sA[kt & 1];
        const float* B = sB[kt & 1];
#pragma unroll
        for (int ks = 0; ks < 2; ks++) {
            int kbv = ks * 8;
            unsigned a[2][4], b[4][2];
#pragma unroll
            for (int mt = 0; mt < 2; mt++) {
                int m = wm * 32 + mt * 16 + gid;
                a[mt][0] = f2tf32(A[m       * ASTRIDE + kbv + tig]);
                a[mt][1] = f2tf32(A[(m + 8) * ASTRIDE + kbv + tig]);
                a[mt][2] = f2tf32(A[m       * ASTRIDE + kbv + tig + 4]);
                a[mt][3] = f2tf32(A[(m + 8) * ASTRIDE + kbv + tig + 4]);
            }
#pragma unroll
            for (int nt = 0; nt < 4; nt++) {
                int n = wn * 32 + nt * 8 + gid;
                b[nt][0] = f2tf32(B[(kbv + tig)     * BSTRIDE + n]);
                b[nt][1] = f2tf32(B[(kbv + tig + 4) * BSTRIDE + n]);
            }
#pragma unroll
            for (int mt = 0; mt < 2; mt++)
#pragma unroll
                for (int nt = 0; nt < 4; nt++)
                    asm volatile(
                        "mma.sync.aligned.m16n8k8.row.col.f32.tf32.tf32.f32 "
                        "{%0,%1,%2,%3}, {%4,%5,%6,%7}, {%8,%9}, {%0,%1,%2,%3};"
                        : "+f"(c[mt][nt][0]), "+f"(c[mt][nt][1]),
                          "+f"(c[mt][nt][2]), "+f"(c[mt][nt][3])
                        : "r"(a[mt][0]), "r"(a[mt][1]), "r"(a[mt][2]), "r"(a[mt][3]),
                          "r"(b[nt][0]), "r"(b[nt][1]));
        }
        __syncthreads();
    }

#pragma unroll
    for (int mt = 0; mt < 2; mt++) {
        int r0 = wm * 32 + mt * 16 + gid;
#pragma unroll
        for (int nt = 0; nt < 4; nt++) {
            int gcol = bn * 64 + wn * 32 + nt * 8 + tig * 2;
            *(float2*)&g_xp[(size_t)(n0 + r0)     * 256 + gcol] =
                make_float2(c[mt][nt][0], c[mt][nt][1]);
            *(float2*)&g_xp[(size_t)(n0 + r0 + 8) * 256 + gcol] =
                make_float2(c[mt][nt][2], c[mt][nt][3]);
        }
    }

    float pl[4] = {0.f, 0.f, 0.f, 0.f};
    float pr[4] = {0.f, 0.f, 0.f, 0.f};
#pragma unroll
    for (int mt = 0; mt < 2; mt++)
#pragma unroll
        for (int nt = 0; nt < 4; nt++) {
            int cl = wn * 32 + nt * 8 + tig * 2;
            float wl0 = sattl[cl], wl1 = sattl[cl + 1];
            float wr0 = sattr[cl], wr1 = sattr[cl + 1];
            pl[mt*2+0] += c[mt][nt][0]*wl0 + c[mt][nt][1]*wl1;
            pl[mt*2+1] += c[mt][nt][2]*wl0 + c[mt][nt][3]*wl1;
            pr[mt*2+0] += c[mt][nt][0]*wr0 + c[mt][nt][1]*wr1;
            pr[mt*2+1] += c[mt][nt][2]*wr0 + c[mt][nt][3]*wr1;
        }
#pragma unroll
    for (int o = 2; o > 0; o >>= 1)
#pragma unroll
        for (int q = 0; q < 4; q++) {
            pl[q] += __shfl_down_sync(0xffffffffu, pl[q], o, 4);
            pr[q] += __shfl_down_sync(0xffffffffu, pr[q], o, 4);
        }
    if (tig == 0) {
#pragma unroll
        for (int mt = 0; mt < 2; mt++)
#pragma unroll
            for (int sb = 0; sb < 2; sb++) {
                int r = wm * 32 + mt * 16 + sb * 8 + gid;
                sredl[wn][r] = pl[mt*2+sb];
                sredr[wn][r] = pr[mt*2+sb];
            }
    }
    __syncthreads();
    if (t < 128) {
        g_al[(n0 + t) * 4 + bn] = sredl[0][t] + sredl[1][t];
        g_ar[(n0 + t) * 4 + bn] = sredr[0][t] + sredr[1][t];
    }
}

// ---------------------------------------------------------------------------
// 5. Gather aggregation: 4 nodes/block, slot-per-node, NO barriers.
//    t = slot*64 + c; thread covers cols c*4..c*4+3 of node (blockIdx.x*4+slot).
__global__ void __launch_bounds__(256) k_agg(
    const float* __restrict__ oh,
    const float* __restrict__ bias,
    float* __restrict__ out)
{
    int t = threadIdx.x;
    int slot = t >> 6;
    int c    = t & 63;
    int col0 = c * 4;
    int h    = c >> 4;
    int n = blockIdx.x * 4 + slot;
    int g = n >> 8;
    const float* ohg = oh + ((size_t)g << 16);

    float arh = g_ar[n * 4 + h];
    int beg = g_off[n];
    int cnt = g_deg[n];

    float4 accx = make_float4(0.f, 0.f, 0.f, 0.f);
    float4 acco = *(const float4*)&ohg[(size_t)(n & 255) * 256 + col0];
    float  den  = 0.f;

    const int* src = g_esrc + beg;
#pragma unroll 2
    for (int i = 0; i < cnt; i++) {
        int s = src[i];
        float l = g_al[s * 4 + h] + arh;
        l = (l > 0.f) ? l : 0.2f * l;              // leaky_relu
        float w = __expf(l);
        den += w;
        float4 xv = *(const float4*)&g_xp[(size_t)s * 256 + col0];
        accx.x = fmaf(w, xv.x, accx.x);
        accx.y = fmaf(w, xv.y, accx.y);
        accx.z = fmaf(w, xv.z, accx.z);
        accx.w = fmaf(w, xv.w, accx.w);
        float4 ov = *(const float4*)&ohg[(size_t)(s & 255) * 256 + col0];
        acco.x += ov.x; acco.y += ov.y; acco.z += ov.z; acco.w += ov.w;
    }

    float inv = 1.0f / (den + 1e-16f);
    float4 bz = *(const float4*)&bias[col0];
    float4 o0 = make_float4(accx.x * inv + bz.x, accx.y * inv + bz.y,
                            accx.z * inv + bz.z, accx.w * inv + bz.w);
    *(float4*)&out[(size_t)n * 256 + col0] = o0;
    *(float4*)&out[(size_t)NN * 256 + (size_t)n * 256 + col0] = acco;
}

// ---------------------------------------------------------------------------
extern "C" void kernel_launch(void* const* d_in, const int* in_sizes, int n_in,
                              void* d_out, int out_size)
{
    const float* x     = (const float*)d_in[0];
    const float* oh    = (const float*)d_in[1];
    const int*   adjs  = (const int*)d_in[2];
    const float* lin_w = (const float*)d_in[3];
    const float* att_l = (const float*)d_in[4];
    const float* att_r = (const float*)d_in[5];
    const float* bias  = (const float*)d_in[6];
    const float* c1w   = (const float*)d_in[7];
    const float* c1b   = (const float*)d_in[8];
    const float* c2w   = (const float*)d_in[9];
    const float* c2b   = (const float*)d_in[10];
    const float* fcw   = (const float*)d_in[11];
    const float* fcb   = (const float*)d_in[12];
    float* out = (float*)d_out;

    // CSR build
    k_csr<<<G_, 256>>>(adjs);
    k_scatter<<<EE / 256, 256>>>(adjs);

    // node features
    k_conv<<<NN / 4, 128>>>(oh, c1w, c1b, c2w, c2b, fcw, fcb);
    dim3 ggrid(NN / 128, 4);
    k_gemm<<<ggrid, 256>>>(x, lin_w, att_l, att_r);

    // aggregation + outputs
    k_agg<<<NN / 4, 256>>>(oh, bias, out);
}

// round 15
// speedup vs baseline: 1.8250x; 1.4808x over previous
#include <cuda_runtime.h>
#include <math.h>

// Problem constants
#define G_    64
#define NPG   256
#define EPG   4096
#define NN    (G_*NPG)     // 16384 nodes
#define EE    (G_*EPG)     // 262144 edges
#define HH    4
#define HC    256
#define KDIM  264

typedef unsigned long long ull;

// Scratch (device globals; no allocation allowed)
__device__ int   g_deg[NN];
__device__ int   g_off[NN];
__device__ int   g_cur[NN];
__device__ int   g_esrc[EE];
__device__ __align__(16) float g_ohfeat[NN*8];
__device__ __align__(16) float g_xp[NN*HC];
__device__ __align__(16) float g_al[NN*HH];
__device__ __align__(16) float g_ar[NN*HH];

__device__ __forceinline__ unsigned f2tf32(float f) {
    unsigned u;
    asm("cvt.rna.tf32.f32 %0, %1;" : "=r"(u) : "f"(f));
    return u;
}

// ---------------------------------------------------------------------------
// 1. Fused CSR prefix: per-graph smem histogram + scan (one block per graph)
__global__ void __launch_bounds__(256) k_csr(const int* __restrict__ adjs) {
    __shared__ int sdeg[NPG];
    __shared__ int s[NPG];
    int g = blockIdx.x, t = threadIdx.x;
    sdeg[t] = 0;
    __syncthreads();
    const int* dsts = adjs + g * 2 * EPG + EPG;
#pragma unroll 4
    for (int e = t; e < EPG; e += 256)
        atomicAdd(&sdeg[dsts[e]], 1);
    __syncthreads();
    int d = sdeg[t];
    s[t] = d;
    for (int o = 1; o < NPG; o <<= 1) {
        __syncthreads();
        int v = (t >= o) ? s[t - o] : 0;
        __syncthreads();
        s[t] += v;
    }
    __syncthreads();
    int off = g * EPG + s[t] - d;   // exclusive prefix + graph base
    g_deg[g * NPG + t] = d;
    g_off[g * NPG + t] = off;
    g_cur[g * NPG + t] = off;
}

// 2. Scatter source ids into CSR slots
__global__ void k_scatter(const int* __restrict__ adjs) {
    int e  = blockIdx.x * 256 + threadIdx.x;
    if (e >= EE) return;
    int g  = e >> 12;
    int le = e & (EPG - 1);
    int base = g * 2 * EPG;
    int src = adjs[base + le];
    int dst = adjs[base + EPG + le];
    int pos = atomicAdd(&g_cur[g * NPG + dst], 1);
    g_esrc[pos] = g * NPG + src;
}

// ---------------------------------------------------------------------------
// 3. Warp-per-node conv, conv2 on tensor cores.
//    Cyclic ownership: lane l, register c hold position c*32 + l.
//    z1 stored position-major z1p[258][stride 9]; conv2 = 96x m16n8k8.tf32.
#define ZSTR 9
__global__ void __launch_bounds__(128) k_conv(
    const float* __restrict__ oh,
    const float* __restrict__ w1, const float* __restrict__ b1,
    const float* __restrict__ w2, const float* __restrict__ b2,
    const float* __restrict__ fcw, const float* __restrict__ fcb)
{
    __shared__ float z1p[4][258 * ZSTR];
    __shared__ float sw2[384];
    __shared__ float sw1[24], sb1[8], sb2[16], sfcw[16 * 8], sfcb[8];
    __shared__ float smean[4][16];

    int t = threadIdx.x;
    int w = t >> 5, l = t & 31;
    int n = blockIdx.x * 4 + w;
    int gid = l >> 2, tig = l & 3;
    float* z1w = &z1p[w][0];

    for (int i = t; i < 384; i += 128) sw2[i] = w2[i];
    if (t < 24)  sw1[t] = w1[t];
    if (t < 8)   sb1[t] = b1[t];
    if (t < 16)  sb2[t] = b2[t];
    if (t < 128) sfcw[t] = fcw[t];
    if (t < 8)   sfcb[t] = fcb[t];
    __syncthreads();

    // ---- load 8 elements, cyclic: v[c] = row[c*32 + l] (coalesced) ----
    const float* ohrow = oh + (size_t)n * 256;
    float v[8];
#pragma unroll
    for (int c = 0; c < 8; c++) v[c] = ohrow[c * 32 + l];

    // ---- bitonic sort of 256, idx = c*32 + l ----
    #define CSP(a_, b_, up) { float _x=(a_), _y=(b_); \
        (a_) = (up)?fminf(_x,_y):fmaxf(_x,_y); \
        (b_) = (up)?fmaxf(_x,_y):fminf(_x,_y); }
    #define SHFL_STEP(j, UPC) { \
        _Pragma("unroll") \
        for (int c = 0; c < 8; c++) { \
            float o = __shfl_xor_sync(0xffffffffu, v[c], (j)); \
            bool up = (UPC); \
            bool lower = ((l & (j)) == 0); \
            v[c] = ((lower == up) ? fminf(v[c], o) : fmaxf(v[c], o)); } }

    // k=2
    SHFL_STEP(1, ((l & 2) == 0))
    // k=4
    SHFL_STEP(2, ((l & 4) == 0))
    SHFL_STEP(1, ((l & 4) == 0))
    // k=8
    SHFL_STEP(4, ((l & 8) == 0))
    SHFL_STEP(2, ((l & 8) == 0))
    SHFL_STEP(1, ((l & 8) == 0))
    // k=16
    SHFL_STEP(8, ((l & 16) == 0))
    SHFL_STEP(4, ((l & 16) == 0))
    SHFL_STEP(2, ((l & 16) == 0))
    SHFL_STEP(1, ((l & 16) == 0))
    // k=32 (dir from c bit 0)
    SHFL_STEP(16, ((c & 1) == 0))
    SHFL_STEP(8,  ((c & 1) == 0))
    SHFL_STEP(4,  ((c & 1) == 0))
    SHFL_STEP(2,  ((c & 1) == 0))
    SHFL_STEP(1,  ((c & 1) == 0))
    // k=64: local j=32 (pairs c^1, dir (c&2)==0), then shfl
    CSP(v[0], v[1], true)  CSP(v[2], v[3], false)
    CSP(v[4], v[5], true)  CSP(v[6], v[7], false)
    SHFL_STEP(16, ((c & 2) == 0))
    SHFL_STEP(8,  ((c & 2) == 0))
    SHFL_STEP(4,  ((c & 2) == 0))
    SHFL_STEP(2,  ((c & 2) == 0))
    SHFL_STEP(1,  ((c & 2) == 0))
    // k=128: local j=64 (pairs c^2, dir (c&4)==0), j=32 (pairs c^1), then shfl
    CSP(v[0], v[2], true)  CSP(v[1], v[3], true)
    CSP(v[4], v[6], false) CSP(v[5], v[7], false)
    CSP(v[0], v[1], true)  CSP(v[2], v[3], true)
    CSP(v[4], v[5], false) CSP(v[6], v[7], false)
    SHFL_STEP(16, ((c & 4) == 0))
    SHFL_STEP(8,  ((c & 4) == 0))
    SHFL_STEP(4,  ((c & 4) == 0))
    SHFL_STEP(2,  ((c & 4) == 0))
    SHFL_STEP(1,  ((c & 4) == 0))
    // k=256 (ascending)
    CSP(v[0], v[4], true) CSP(v[1], v[5], true)
    CSP(v[2], v[6], true) CSP(v[3], v[7], true)
    CSP(v[0], v[2], true) CSP(v[1], v[3], true)
    CSP(v[4], v[6], true) CSP(v[5], v[7], true)
    CSP(v[0], v[1], true) CSP(v[2], v[3], true)
    CSP(v[4], v[5], true) CSP(v[6], v[7], true)
    SHFL_STEP(16, true)
    SHFL_STEP(8,  true)
    SHFL_STEP(4,  true)
    SHFL_STEP(2,  true)
    SHFL_STEP(1,  true)

    // ---- conv1 halos via shfl (cyclic: p-1 = lane l-1 same c; wrap chunks) ----
    float lf[8], rt[8];
#pragma unroll
    for (int c = 0; c < 8; c++) {
        lf[c] = __shfl_up_sync(0xffffffffu, v[c], 1);
        rt[c] = __shfl_down_sync(0xffffffffu, v[c], 1);
    }
#pragma unroll
    for (int c = 0; c < 8; c++) {
        float prev31 = (c > 0) ? __shfl_sync(0xffffffffu, v[c - 1], 31) : 0.f;
        float next0  = (c < 7) ? __shfl_sync(0xffffffffu, v[c + 1], 0)  : 0.f;
        if (l == 0)  lf[c] = prev31;
        if (l == 31) rt[c] = next0;
    }

    // zero padding rows of z1p (rows 0 and 257)
    if (l < 8)            z1w[0 * ZSTR + l] = 0.f;
    else if (l < 16)      z1w[257 * ZSTR + (l - 8)] = 0.f;

    // ---- conv1 -> z1p[pos+1][ic] (lane stride 9: conflict-free STS) ----
#pragma unroll
    for (int ic = 0; ic < 8; ic++) {
        float w0 = sw1[ic*3 + 0], w1c = sw1[ic*3 + 1], w2c = sw1[ic*3 + 2];
        float bb = sb1[ic];
#pragma unroll
        for (int c = 0; c < 8; c++) {
            float z = fmaxf(bb + w0*lf[c] + w1c*v[c] + w2c*rt[c], 0.f);
            z1w[(c * 32 + l + 1) * ZSTR + ic] = z;
        }
    }
    __syncwarp();

    // ---- conv2 via m16n8k8.tf32: A[pos][k=j*8+ic] = z1p[pos+j][ic] ----
    // B[k=j*8+ic][oc] = w2[oc*24 + ic*3 + j]
    unsigned bf[3][2][2];
#pragma unroll
    for (int kt = 0; kt < 3; kt++)
#pragma unroll
        for (int nt = 0; nt < 2; nt++) {
            bf[kt][nt][0] = f2tf32(sw2[(nt*8 + gid) * 24 + tig * 3 + kt]);
            bf[kt][nt][1] = f2tf32(sw2[(nt*8 + gid) * 24 + (tig + 4) * 3 + kt]);
        }
    float b2ch[2][2];
#pragma unroll
    for (int nt = 0; nt < 2; nt++) {
        b2ch[nt][0] = sb2[nt*8 + tig*2 + 0];
        b2ch[nt][1] = sb2[nt*8 + tig*2 + 1];
    }

    float macc[2][2] = {{0.f, 0.f}, {0.f, 0.f}};
#pragma unroll
    for (int mt = 0; mt < 16; mt++) {
        int m0 = mt * 16;
        float cc[2][4] = {{0.f,0.f,0.f,0.f},{0.f,0.f,0.f,0.f}};
#pragma unroll
        for (int kt = 0; kt < 3; kt++) {
            unsigned a0 = f2tf32(z1w[(m0 + gid     + kt) * ZSTR + tig]);
            unsigned a1 = f2tf32(z1w[(m0 + gid + 8 + kt) * ZSTR + tig]);
            unsigned a2 = f2tf32(z1w[(m0 + gid     + kt) * ZSTR + tig + 4]);
            unsigned a3 = f2tf32(z1w[(m0 + gid + 8 + kt) * ZSTR + tig + 4]);
#pragma unroll
            for (int nt = 0; nt < 2; nt++)
                asm volatile(
                    "mma.sync.aligned.m16n8k8.row.col.f32.tf32.tf32.f32 "
                    "{%0,%1,%2,%3}, {%4,%5,%6,%7}, {%8,%9}, {%0,%1,%2,%3};"
                    : "+f"(cc[nt][0]), "+f"(cc[nt][1]),
                      "+f"(cc[nt][2]), "+f"(cc[nt][3])
                    : "r"(a0), "r"(a1), "r"(a2), "r"(a3),
                      "r"(bf[kt][nt][0]), "r"(bf[kt][nt][1]));
        }
#pragma unroll
        for (int nt = 0; nt < 2; nt++) {
            macc[nt][0] += fmaxf(cc[nt][0] + b2ch[nt][0], 0.f)
                         + fmaxf(cc[nt][2] + b2ch[nt][0], 0.f);
            macc[nt][1] += fmaxf(cc[nt][1] + b2ch[nt][1], 0.f)
                         + fmaxf(cc[nt][3] + b2ch[nt][1], 0.f);
        }
    }

    // reduce across gid (lane bits 2,3,4)
#pragma unroll
    for (int o = 4; o <= 16; o <<= 1)
#pragma unroll
        for (int nt = 0; nt < 2; nt++) {
            macc[nt][0] += __shfl_xor_sync(0xffffffffu, macc[nt][0], o);
            macc[nt][1] += __shfl_xor_sync(0xffffffffu, macc[nt][1], o);
        }
    if (gid == 0) {
        smean[w][tig*2 + 0]     = macc[0][0] * (1.0f / 256.0f);
        smean[w][tig*2 + 1]     = macc[0][1] * (1.0f / 256.0f);
        smean[w][8 + tig*2 + 0] = macc[1][0] * (1.0f / 256.0f);
        smean[w][8 + tig*2 + 1] = macc[1][1] * (1.0f / 256.0f);
    }
    __syncwarp();

    // ---- fc (8 outputs) ----
    if (l < 8) {
        float z = sfcb[l];
#pragma unroll
        for (int ic = 0; ic < 16; ic++) z = fmaf(smean[w][ic], sfcw[ic * 8 + l], z);
        g_ohfeat[n * 8 + l] = z;
    }
}

// ---------------------------------------------------------------------------
// 4. Tensor-core GEMM with cp.async double buffering (unchanged from R7).
__device__ __forceinline__ void cpa16(unsigned d, const void* s, int srcsize) {
    asm volatile("cp.async.cg.shared.global [%0], [%1], 16, %2;"
                 :: "r"(d), "l"(s), "r"(srcsize));
}

#define ASTRIDE 20
#define BSTRIDE 72

__global__ void __launch_bounds__(256) k_gemm(
    const float* __restrict__ x, const float* __restrict__ lw,
    const float* __restrict__ attl, const float* __restrict__ attr)
{
    __shared__ float sA[2][128 * ASTRIDE];
    __shared__ float sB[2][16 * BSTRIDE];
    __shared__ float sattl[64], sattr[64];
    __shared__ float sredl[2][128], sredr[2][128];

    int t  = threadIdx.x;
    int bm = blockIdx.x, bn = blockIdx.y;      // bn == head
    int n0 = bm * 128;
    int w = t >> 5, lane = t & 31;
    int wm = w & 3, wn = w >> 2;
    int gid = lane >> 2, tig = lane & 3;

    if (t < 64) { sattl[t] = attl[bn * 64 + t]; sattr[t] = attr[bn * 64 + t]; }

    unsigned sAaddr[2], sBaddr[2];
    sAaddr[0] = (unsigned)__cvta_generic_to_shared(&sA[0][0]);
    sAaddr[1] = (unsigned)__cvta_generic_to_shared(&sA[1][0]);
    sBaddr[0] = (unsigned)__cvta_generic_to_shared(&sB[0][0]);
    sBaddr[1] = (unsigned)__cvta_generic_to_shared(&sB[1][0]);

    int ar0 = t >> 2,            ac0 = (t & 3) * 4;
    int ar1 = (t + 256) >> 2,    ac1 = (t & 3) * 4;
    int br  = t >> 4,            bc  = (t & 15) * 4;

    auto stage = [&](int kt) {
        int b = kt & 1;
        unsigned da0 = sAaddr[b] + (ar0 * ASTRIDE + ac0) * 4;
        unsigned da1 = sAaddr[b] + (ar1 * ASTRIDE + ac1) * 4;
        unsigned db  = sBaddr[b] + (br  * BSTRIDE + bc ) * 4;
        if (kt < 16) {
            cpa16(da0, x + (size_t)(n0 + ar0) * 256 + kt * 16 + ac0, 16);
            cpa16(da1, x + (size_t)(n0 + ar1) * 256 + kt * 16 + ac1, 16);
            cpa16(db,  lw + (size_t)(kt * 16 + br) * 256 + bn * 64 + bc, 16);
        } else {
            cpa16(da0, (ac0 < 8) ? (const void*)(g_ohfeat + (n0 + ar0) * 8 + ac0)
                                 : (const void*)g_ohfeat, (ac0 < 8) ? 16 : 0);
            cpa16(da1, (ac1 < 8) ? (const void*)(g_ohfeat + (n0 + ar1) * 8 + ac1)
                                 : (const void*)g_ohfeat, (ac1 < 8) ? 16 : 0);
            cpa16(db,  (br < 8) ? (const void*)(lw + (size_t)(256 + br) * 256 + bn * 64 + bc)
                                : (const void*)lw, (br < 8) ? 16 : 0);
        }
        asm volatile("cp.async.commit_group;");
    };

    float c[2][4][4];
#pragma unroll
    for (int mt = 0; mt < 2; mt++)
#pragma unroll
        for (int nt = 0; nt < 4; nt++)
#pragma unroll
            for (int q = 0; q < 4; q++) c[mt][nt][q] = 0.f;

    stage(0);

    for (int kt = 0; kt < 17; kt++) {
        asm volatile("cp.async.wait_group 0;");
        __syncthreads();
        if (kt < 16) stage(kt + 1);

        const float* A = sA[kt & 1];
        const float* B = sB[kt & 1];
#pragma unroll
        for (int ks = 0; ks < 2; ks++) {
            int kbv = ks * 8;
            unsigned a[2][4], b[4][2];
#pragma unroll
            for (int mt = 0; mt < 2; mt++) {
                int m = wm * 32 + mt * 16 + gid;
                a[mt][0] = f2tf32(A[m       * ASTRIDE + kbv + tig]);
                a[mt][1] = f2tf32(A[(m + 8) * ASTRIDE + kbv + tig]);
                a[mt][2] = f2tf32(A[m       * ASTRIDE + kbv + tig + 4]);
                a[mt][3] = f2tf32(A[(m + 8) * ASTRIDE + kbv + tig + 4]);
            }
#pragma unroll
            for (int nt = 0; nt < 4; nt++) {
                int n = wn * 32 + nt * 8 + gid;
                b[nt][0] = f2tf32(B[(kbv + tig)     * BSTRIDE + n]);
                b[nt][1] = f2tf32(B[(kbv + tig + 4) * BSTRIDE + n]);
            }
#pragma unroll
            for (int mt = 0; mt < 2; mt++)
#pragma unroll
                for (int nt = 0; nt < 4; nt++)
                    asm volatile(
                        "mma.sync.aligned.m16n8k8.row.col.f32.tf32.tf32.f32 "
                        "{%0,%1,%2,%3}, {%4,%5,%6,%7}, {%8,%9}, {%0,%1,%2,%3};"
                        : "+f"(c[mt][nt][0]), "+f"(c[mt][nt][1]),
                          "+f"(c[mt][nt][2]), "+f"(c[mt][nt][3])
                        : "r"(a[mt][0]), "r"(a[mt][1]), "r"(a[mt][2]), "r"(a[mt][3]),
                          "r"(b[nt][0]), "r"(b[nt][1]));
        }
        __syncthreads();
    }

#pragma unroll
    for (int mt = 0; mt < 2; mt++) {
        int r0 = wm * 32 + mt * 16 + gid;
#pragma unroll
        for (int nt = 0; nt < 4; nt++) {
            int gcol = bn * 64 + wn * 32 + nt * 8 + tig * 2;
            *(float2*)&g_xp[(size_t)(n0 + r0)     * 256 + gcol] =
                make_float2(c[mt][nt][0], c[mt][nt][1]);
            *(float2*)&g_xp[(size_t)(n0 + r0 + 8) * 256 + gcol] =
                make_float2(c[mt][nt][2], c[mt][nt][3]);
        }
    }

    float pl[4] = {0.f, 0.f, 0.f, 0.f};
    float pr[4] = {0.f, 0.f, 0.f, 0.f};
#pragma unroll
    for (int mt = 0; mt < 2; mt++)
#pragma unroll
        for (int nt = 0; nt < 4; nt++) {
            int cl = wn * 32 + nt * 8 + tig * 2;
            float wl0 = sattl[cl], wl1 = sattl[cl + 1];
            float wr0 = sattr[cl], wr1 = sattr[cl + 1];
            pl[mt*2+0] += c[mt][nt][0]*wl0 + c[mt][nt][1]*wl1;
            pl[mt*2+1] += c[mt][nt][2]*wl0 + c[mt][nt][3]*wl1;
            pr[mt*2+0] += c[mt][nt][0]*wr0 + c[mt][nt][1]*wr1;
            pr[mt*2+1] += c[mt][nt][2]*wr0 + c[mt][nt][3]*wr1;
        }
#pragma unroll
    for (int o = 2; o > 0; o >>= 1)
#pragma unroll
        for (int q = 0; q < 4; q++) {
            pl[q] += __shfl_down_sync(0xffffffffu, pl[q], o, 4);
            pr[q] += __shfl_down_sync(0xffffffffu, pr[q], o, 4);
        }
    if (tig == 0) {
#pragma unroll
        for (int mt = 0; mt < 2; mt++)
#pragma unroll
            for (int sb = 0; sb < 2; sb++) {
                int r = wm * 32 + mt * 16 + sb * 8 + gid;
                sredl[wn][r] = pl[mt*2+sb];
                sredr[wn][r] = pr[mt*2+sb];
            }
    }
    __syncthreads();
    if (t < 128) {
        g_al[(n0 + t) * 4 + bn] = sredl[0][t] + sredl[1][t];
        g_ar[(n0 + t) * 4 + bn] = sredr[0][t] + sredr[1][t];
    }
}

// ---------------------------------------------------------------------------
// 5. Gather aggregation: 4 nodes/block, slot-per-node, NO barriers.
__global__ void __launch_bounds__(256) k_agg(
    const float* __restrict__ oh,
    const float* __restrict__ bias,
    float* __restrict__ out)
{
    int t = threadIdx.x;
    int slot = t >> 6;
    int c    = t & 63;
    int col0 = c * 4;
    int h    = c >> 4;
    int n = blockIdx.x * 4 + slot;
    int g = n >> 8;
    const float* ohg = oh + ((size_t)g << 16);

    float arh = g_ar[n * 4 + h];
    int beg = g_off[n];
    int cnt = g_deg[n];

    float4 accx = make_float4(0.f, 0.f, 0.f, 0.f);
    float4 acco = *(const float4*)&ohg[(size_t)(n & 255) * 256 + col0];
    float  den  = 0.f;

    const int* src = g_esrc + beg;
#pragma unroll 2
    for (int i = 0; i < cnt; i++) {
        int s = src[i];
        float l = g_al[s * 4 + h] + arh;
        l = (l > 0.f) ? l : 0.2f * l;              // leaky_relu
        float w = __expf(l);
        den += w;
        float4 xv = *(const float4*)&g_xp[(size_t)s * 256 + col0];
        accx.x = fmaf(w, xv.x, accx.x);
        accx.y = fmaf(w, xv.y, accx.y);
        accx.z = fmaf(w, xv.z, accx.z);
        accx.w = fmaf(w, xv.w, accx.w);
        float4 ov = *(const float4*)&ohg[(size_t)(s & 255) * 256 + col0];
        acco.x += ov.x; acco.y += ov.y; acco.z += ov.z; acco.w += ov.w;
    }

    float inv = 1.0f / (den + 1e-16f);
    float4 bz = *(const float4*)&bias[col0];
    float4 o0 = make_float4(accx.x * inv + bz.x, accx.y * inv + bz.y,
                            accx.z * inv + bz.z, accx.w * inv + bz.w);
    *(float4*)&out[(size_t)n * 256 + col0] = o0;
    *(float4*)&out[(size_t)NN * 256 + (size_t)n * 256 + col0] = acco;
}

// ---------------------------------------------------------------------------
extern "C" void kernel_launch(void* const* d_in, const int* in_sizes, int n_in,
                              void* d_out, int out_size)
{
    const float* x     = (const float*)d_in[0];
    const float* oh    = (const float*)d_in[1];
    const int*   adjs  = (const int*)d_in[2];
    const float* lin_w = (const float*)d_in[3];
    const float* att_l = (const float*)d_in[4];
    const float* att_r = (const float*)d_in[5];
    const float* bias  = (const float*)d_in[6];
    const float* c1w   = (const float*)d_in[7];
    const float* c1b   = (const float*)d_in[8];
    const float* c2w   = (const float*)d_in[9];
    const float* c2b   = (const float*)d_in[10];
    const float* fcw   = (const float*)d_in[11];
    const float* fcb   = (const float*)d_in[12];
    float* out = (float*)d_out;

    // CSR build
    k_csr<<<G_, 256>>>(adjs);
    k_scatter<<<EE / 256, 256>>>(adjs);

    // node features
    k_conv<<<NN / 4, 128>>>(oh, c1w, c1b, c2w, c2b, fcw, fcb);
    dim3 ggrid(NN / 128, 4);
    k_gemm<<<ggrid, 256>>>(x, lin_w, att_l, att_r);

    // aggregation + outputs
    k_agg<<<NN / 4, 256>>>(oh, bias, out);
}